// round 15
// baseline (speedup 1.0000x reference)
#include <cuda_runtime.h>
#include <math.h>

#define B_   32
#define DF_  2048
#define NC_  1023
#define NCP_ 1024

typedef unsigned long long ull;

// ---- packed f32x2 helpers ----
__device__ __forceinline__ ull PK(float lo, float hi) {
    ull r; asm("mov.b64 %0,{%1,%2};" : "=l"(r) : "f"(lo), "f"(hi)); return r;
}
__device__ __forceinline__ void UPK(ull v, float& a, float& b) {
    asm("mov.b64 {%0,%1},%2;" : "=f"(a), "=f"(b) : "l"(v));
}
__device__ __forceinline__ ull FMA2(ull a, ull b, ull c) {
    ull d; asm("fma.rn.f32x2 %0,%1,%2,%3;" : "=l"(d) : "l"(a), "l"(b), "l"(c)); return d;
}
__device__ __forceinline__ ull ADD2(ull a, ull b) {
    ull d; asm("add.rn.f32x2 %0,%1,%2;" : "=l"(d) : "l"(a), "l"(b)); return d;
}
__device__ __forceinline__ ull MUL2(ull a, ull b) {
    ull d; asm("mul.rn.f32x2 %0,%1,%2;" : "=l"(d) : "l"(a), "l"(b)); return d;
}

// ---- cp.async helpers ----
__device__ __forceinline__ void cpasync16(void* dst_smem, const void* src) {
    unsigned d = (unsigned)__cvta_generic_to_shared(dst_smem);
    asm volatile("cp.async.cg.shared.global [%0], [%1], 16;" :: "r"(d), "l"(src));
}
__device__ __forceinline__ void cp_commit() {
    asm volatile("cp.async.commit_group;");
}
template <int N>
__device__ __forceinline__ void cp_wait() {
    asm volatile("cp.async.wait_group %0;" :: "n"(N));
}

// ---------------- scratch ----------------
__device__ float g_LN[B_ * DF_];
__device__ float g_S[B_ * NCP_];
__device__ float g_V[B_ * NCP_];
__device__ float g_smax[B_];
__device__ float g_smin[B_];
__device__ float g_OUT1[B_ * DF_];
__device__ float g_LN2[B_ * DF_];
__device__ float g_H[B_ * DF_];

// ============================================================================
// K0: L2 prefetch of W1+W2 (runs on forked stream under prep+attn)
// ============================================================================
__global__ __launch_bounds__(256) void prefetch_kernel(const float* __restrict__ w1,
                                                       const float* __restrict__ w2) {
    size_t i = ((size_t)blockIdx.x * 256 + threadIdx.x) * 32;   // 128B lines
    const size_t stride = (size_t)gridDim.x * 256 * 32;
    #pragma unroll
    for (int j = 0; j < 4; ++j) {
        asm volatile("prefetch.global.L2 [%0];" :: "l"(w1 + i));
        asm volatile("prefetch.global.L2 [%0];" :: "l"(w2 + i));
        i += stride;
    }
}

// ============================================================================
// K1: per-batch preprocess (round-5, unchanged)
// ============================================================================
__global__ void prep_kernel(const float* __restrict__ feat,
                            const int*   __restrict__ idx,
                            const float* __restrict__ ln_w,
                            const float* __restrict__ ln_b,
                            const float* __restrict__ q_w,
                            const float* __restrict__ k_w,
                            const float* __restrict__ v_w,
                            const float* __restrict__ conv_w) {
    __shared__ float sf[DF_];
    __shared__ float sh[DF_];
    __shared__ float kred[4][128];
    __shared__ float vred[4][128];
    __shared__ float red1[8], red2[8];

    const int b = blockIdx.x;
    const int tid = threadIdx.x;

    float s1 = 0.f, s2 = 0.f;
    for (int i = tid; i < DF_; i += 256) {
        float v = feat[b * DF_ + i];
        sf[i] = v;
        s1 += v;
        s2 = fmaf(v, v, s2);
    }

    if (tid < 128) {
        float qw = q_w[tid];
        float cw = conv_w[tid];
        #pragma unroll
        for (int j = 0; j < 4; j++) {
            kred[j][tid] = qw * k_w[tid * 4 + j];
            vred[j][tid] = cw * v_w[tid * 4 + j];
        }
    }

    #pragma unroll
    for (int o = 16; o; o >>= 1) {
        s1 += __shfl_xor_sync(~0u, s1, o);
        s2 += __shfl_xor_sync(~0u, s2, o);
    }
    if ((tid & 31) == 0) { red1[tid >> 5] = s1; red2[tid >> 5] = s2; }
    __syncthreads();

    if (tid < 64) {
        #pragma unroll
        for (int j = 0; j < 4; j++) {
            kred[j][tid] += kred[j][tid + 64];
            vred[j][tid] += vred[j][tid + 64];
        }
    }
    __syncthreads();
    if (tid < 32) {
        #pragma unroll
        for (int j = 0; j < 4; j++) {
            float kv = kred[j][tid] + kred[j][tid + 32];
            float vv = vred[j][tid] + vred[j][tid + 32];
            #pragma unroll
            for (int o = 16; o; o >>= 1) {
                kv += __shfl_xor_sync(~0u, kv, o);
                vv += __shfl_xor_sync(~0u, vv, o);
            }
            if (tid == 0) { kred[j][0] = kv; vred[j][0] = vv; }
        }
    }
    __syncthreads();

    float S1 = 0.f, S2 = 0.f;
    #pragma unroll
    for (int i = 0; i < 8; i++) { S1 += red1[i]; S2 += red2[i]; }
    const float mean = S1 * (1.f / DF_);
    const float var  = S2 * (1.f / DF_) - mean * mean;
    const float rstd = rsqrtf(var + 1e-5f);

    for (int i = tid; i < DF_; i += 256) {
        g_LN[b * DF_ + i] = (sf[i] - mean) * rstd * ln_w[i] + ln_b[i];
        sh[i] = sf[idx[i]];
    }
    __syncthreads();

    const float kw0 = kred[0][0], kw1 = kred[1][0], kw2 = kred[2][0], kw3 = kred[3][0];
    const float vw0 = vred[0][0], vw1 = vred[1][0], vw2 = vred[2][0], vw3 = vred[3][0];

    float lmax = -3.4e38f, lmin = 3.4e38f;
    for (int c = tid; c < NCP_; c += 256) {
        float s = 0.f, v = 0.f;
        if (c < NC_) {
            float x0 = sh[2 * c], x1 = sh[2 * c + 1], x2 = sh[2 * c + 2], x3 = sh[2 * c + 3];
            s = fmaf(x3, kw3, fmaf(x2, kw2, fmaf(x1, kw1, x0 * kw0)));
            v = fmaf(x3, vw3, fmaf(x2, vw2, fmaf(x1, vw1, x0 * vw0)));
            lmax = fmaxf(lmax, s);
            lmin = fminf(lmin, s);
        }
        g_S[b * NCP_ + c] = s;
        g_V[b * NCP_ + c] = v;
    }
    #pragma unroll
    for (int o = 16; o; o >>= 1) {
        lmax = fmaxf(lmax, __shfl_xor_sync(~0u, lmax, o));
        lmin = fminf(lmin, __shfl_xor_sync(~0u, lmin, o));
    }
    __syncthreads();
    if ((tid & 31) == 0) { red1[tid >> 5] = lmax; red2[tid >> 5] = lmin; }
    __syncthreads();
    if (tid == 0) {
        float mx = red1[0], mn = red2[0];
        #pragma unroll
        for (int i = 1; i < 8; i++) { mx = fmaxf(mx, red1[i]); mn = fminf(mn, red2[i]); }
        g_smax[b] = mx;
        g_smin[b] = mn;
    }
}

// ============================================================================
// K2: softmax + attn output (round-5: reg S/V + smem staged aligned stores)
// ============================================================================
#define SBUF_PITCH 1056
__global__ __launch_bounds__(256) void attn_kernel(const float* __restrict__ feat,
                                                   float* __restrict__ dout) {
    __shared__ __align__(16) float sbuf[8 * SBUF_PITCH];

    const int b = blockIdx.x;
    const int chunk = blockIdx.y;
    const int tid = threadIdx.x;
    const int lane = tid & 31;
    const int w = tid >> 5;

    const float2* gs = (const float2*)(g_S + b * NCP_);
    const float2* gv = (const float2*)(g_V + b * NCP_);
    ull sreg[16], vreg[16];
    #pragma unroll
    for (int i = 0; i < 16; ++i) {
        float2 s2 = gs[lane + 32 * i];
        float2 v2 = gv[lane + 32 * i];
        sreg[i] = PK(s2.x, s2.y);
        vreg[i] = PK(v2.x, v2.y);
    }

    const float smax = g_smax[b];
    const float smin = g_smin[b];
    const float LOG2E = 1.4426950408889634f;
    const ull C5 = PK(0.00133335581464284f, 0.00133335581464284f);
    const ull C4 = PK(0.00961812910762848f, 0.00961812910762848f);
    const ull C3 = PK(0.05550410866482158f, 0.05550410866482158f);
    const ull C2 = PK(0.24022650695910071f, 0.24022650695910071f);
    const ull C1 = PK(0.69314718055994531f, 0.69314718055994531f);
    const ull ONE = PK(1.0f, 1.0f);

    const bool lastlane = (lane == 31);
    float* const sb = sbuf + w * SBUF_PITCH;

    for (int r = 0; r < 16; ++r) {
        const int q = chunk * 128 + r * 8 + w;
        const int row = b * DF_ + q;
        const float alpha = g_LN[row];
        const float al = alpha * LOG2E;
        const float m = (alpha >= 0.f) ? smax : smin;
        const float nb = -al * m;
        const ull al2 = PK(al, al);
        const ull nb2 = PK(nb, nb);

        ull p2[16];
        ull sum2 = PK(0.f, 0.f), dot2 = PK(0.f, 0.f);
        #pragma unroll
        for (int i = 0; i < 16; ++i) {
            ull x = FMA2(al2, sreg[i], nb2);
            ull pf = FMA2(x, C5, C4);
            pf = FMA2(x, pf, C3);
            pf = FMA2(x, pf, C2);
            pf = FMA2(x, pf, C1);
            pf = FMA2(x, pf, ONE);
            if (i == 15) {
                float a_, b_; UPK(pf, a_, b_);
                if (lastlane) b_ = 0.f;
                pf = PK(a_, b_);
            }
            p2[i] = pf;
            sum2 = ADD2(sum2, pf);
            dot2 = FMA2(pf, vreg[i], dot2);
        }

        float slo, shi, dlo, dhi;
        UPK(sum2, slo, shi);
        UPK(dot2, dlo, dhi);
        float sum = slo + shi;
        float dot = dlo + dhi;
        #pragma unroll
        for (int o = 16; o; o >>= 1) {
            sum += __shfl_xor_sync(~0u, sum, o);
            dot += __shfl_xor_sync(~0u, dot, o);
        }
        const float inv = 1.0f / sum;
        const ull inv2 = PK(inv, inv);

        float* const base = dout + 65536 + (size_t)row * NC_;
        const int shift = (int)((size_t)base & 15) >> 2;
        const int lead = (4 - shift) & 3;

        if ((shift & 1) == 0) {
            #pragma unroll
            for (int i = 0; i < 16; ++i) {
                float o0, o1; UPK(MUL2(p2[i], inv2), o0, o1);
                *(float2*)(sb + 2 * (lane + 32 * i) + shift) = make_float2(o0, o1);
            }
        } else {
            #pragma unroll
            for (int i = 0; i < 16; ++i) {
                float o0, o1; UPK(MUL2(p2[i], inv2), o0, o1);
                const int c = 2 * (lane + 32 * i) + shift;
                sb[c] = o0;
                sb[c + 1] = o1;
            }
        }
        __syncwarp();

        if (lane < lead) __stcs(base + lane, sb[lane + shift]);
        const float4* s4 = (const float4*)(sb + lead + shift);
        float4* g4 = (float4*)(base + lead);
        #pragma unroll
        for (int j = 0; j < 8; ++j) {
            const int t = lane + 32 * j;
            if (t < 255) __stcs(g4 + t, s4[t]);
        }
        const int done = lead + 1020;
        const int tail = NC_ - done;
        if (lane < tail) __stcs(base + done + lane, sb[done + lane + shift]);

        if (lane == 0) {
            g_OUT1[row] = fmaf(dot, inv, feat[row]);
        }
        __syncwarp();
    }
}

// ============================================================================
// K3: FFN prep (round-5, unchanged)
// ============================================================================
__global__ void ffn_prep_kernel(const float* __restrict__ bn_w,
                                const float* __restrict__ bn_b,
                                const float* __restrict__ w1_b,
                                const float* __restrict__ w2_b,
                                float* __restrict__ dout) {
    __shared__ float row[DF_];
    __shared__ float red1[8], red2[8];
    const int m = blockIdx.x;
    const int tid = threadIdx.x;

    float s1 = 0.f, s2 = 0.f;
    for (int i = tid; i < DF_; i += 256) {
        float v = g_OUT1[m * DF_ + i];
        row[i] = v;
        s1 += v;
        s2 = fmaf(v, v, s2);
    }
    #pragma unroll
    for (int o = 16; o; o >>= 1) {
        s1 += __shfl_xor_sync(~0u, s1, o);
        s2 += __shfl_xor_sync(~0u, s2, o);
    }
    if ((tid & 31) == 0) { red1[tid >> 5] = s1; red2[tid >> 5] = s2; }
    __syncthreads();
    float S1 = 0.f, S2 = 0.f;
    #pragma unroll
    for (int i = 0; i < 8; i++) { S1 += red1[i]; S2 += red2[i]; }
    const float mean = S1 * (1.f / DF_);
    const float var  = S2 * (1.f / DF_) - mean * mean;
    const float rstd = rsqrtf(var + 1e-6f);

    for (int i = tid; i < DF_; i += 256) {
        g_LN2[m * DF_ + i] = (row[i] - mean) * rstd * bn_w[i] + bn_b[i];
        g_H[m * DF_ + i]   = w1_b[i];
        dout[m * DF_ + i]  = w2_b[i] + row[i];
    }
}

// ============================================================================
// K4/K5: GEMM (round-5 config: 32m x 128n x 256k, grid (16,8), f32x2 FMA)
// ============================================================================
__global__ __launch_bounds__(256) void gemm_kernel(int mode,
                                                   const float* __restrict__ W,
                                                   float* __restrict__ outp) {
    __shared__ __align__(16) float As[256][36];        // [k][m]
    __shared__ __align__(16) float Ws[3][128][36];     // [n][k] stages

    const float* A = (mode == 0) ? g_LN2 : g_H;
    float* C       = (mode == 0) ? g_H   : outp;

    const int n0 = blockIdx.x * 128;
    const int k0 = blockIdx.y * 256;
    const int tid = threadIdx.x;
    const int lane = tid & 31;
    const int wid = tid >> 5;

    auto issueW = [&](int s) {
        const int buf = s % 3;
        #pragma unroll
        for (int j = 0; j < 4; ++j) {
            int idx = tid + 256 * j;
            int n = idx >> 3, qd = idx & 7;
            cpasync16(&Ws[buf][n][qd * 4],
                      &W[(size_t)(n0 + n) * DF_ + k0 + s * 32 + qd * 4]);
        }
        cp_commit();
    };

    issueW(0);
    issueW(1);

    {
        const int m = tid >> 3;
        const int kq = (tid & 7) * 4;
        #pragma unroll
        for (int it = 0; it < 8; ++it) {
            const int k = kq + 32 * it;
            float4 v = *(const float4*)&A[m * DF_ + k0 + k];
            if (mode) {
                v.x = fmaxf(v.x, 0.f); v.y = fmaxf(v.y, 0.f);
                v.z = fmaxf(v.z, 0.f); v.w = fmaxf(v.w, 0.f);
            }
            As[k + 0][m] = v.x;
            As[k + 1][m] = v.y;
            As[k + 2][m] = v.z;
            As[k + 3][m] = v.w;
        }
    }

    const int m0 = (lane & 7) * 4;
    const int nb = wid * 16 + (lane >> 3) * 4;

    ull acc2[4][2];
    #pragma unroll
    for (int u = 0; u < 4; ++u) { acc2[u][0] = PK(0.f, 0.f); acc2[u][1] = PK(0.f, 0.f); }

    #pragma unroll
    for (int s = 0; s < 8; ++s) {
        if (s < 7) cp_wait<1>(); else cp_wait<0>();
        __syncthreads();
        if (s + 2 < 8) issueW(s + 2);

        const int buf = s % 3;
        #pragma unroll
        for (int k4 = 0; k4 < 8; ++k4) {
            const int kk = s * 32 + k4 * 4;
            ull a[4][2];
            #pragma unroll
            for (int k = 0; k < 4; ++k) {
                float4 av = *(const float4*)&As[kk + k][m0];
                a[k][0] = PK(av.x, av.y);
                a[k][1] = PK(av.z, av.w);
            }
            #pragma unroll
            for (int u = 0; u < 4; ++u) {
                float4 wv = *(const float4*)&Ws[buf][nb + u][k4 * 4];
                ull w0 = PK(wv.x, wv.x);
                ull w1 = PK(wv.y, wv.y);
                ull w2 = PK(wv.z, wv.z);
                ull w3 = PK(wv.w, wv.w);
                acc2[u][0] = FMA2(a[0][0], w0, acc2[u][0]);
                acc2[u][1] = FMA2(a[0][1], w0, acc2[u][1]);
                acc2[u][0] = FMA2(a[1][0], w1, acc2[u][0]);
                acc2[u][1] = FMA2(a[1][1], w1, acc2[u][1]);
                acc2[u][0] = FMA2(a[2][0], w2, acc2[u][0]);
                acc2[u][1] = FMA2(a[2][1], w2, acc2[u][1]);
                acc2[u][0] = FMA2(a[3][0], w3, acc2[u][0]);
                acc2[u][1] = FMA2(a[3][1], w3, acc2[u][1]);
            }
        }
    }

    #pragma unroll
    for (int u = 0; u < 4; ++u) {
        float v0, v1, v2, v3;
        UPK(acc2[u][0], v0, v1);
        UPK(acc2[u][1], v2, v3);
        atomicAdd(&C[(m0 + 0) * DF_ + n0 + nb + u], v0);
        atomicAdd(&C[(m0 + 1) * DF_ + n0 + nb + u], v1);
        atomicAdd(&C[(m0 + 2) * DF_ + n0 + nb + u], v2);
        atomicAdd(&C[(m0 + 3) * DF_ + n0 + nb + u], v3);
    }
}

// ============================================================================
extern "C" void kernel_launch(void* const* d_in, const int* in_sizes, int n_in,
                              void* d_out, int out_size) {
    const float* feat   = (const float*)d_in[0];
    const int*   idx    = (const int*)  d_in[1];
    const float* ln_w   = (const float*)d_in[2];
    const float* ln_b   = (const float*)d_in[3];
    const float* q_w    = (const float*)d_in[4];
    const float* k_w    = (const float*)d_in[5];
    const float* v_w    = (const float*)d_in[6];
    const float* conv_w = (const float*)d_in[7];
    const float* bn_w   = (const float*)d_in[8];
    const float* bn_b   = (const float*)d_in[9];
    const float* w1_w   = (const float*)d_in[10];
    const float* w1_b   = (const float*)d_in[11];
    const float* w2_w   = (const float*)d_in[12];
    const float* w2_b   = (const float*)d_in[13];
    float* out = (float*)d_out;

    // side stream + events for the L2 weight prefetch (created once, reused;
    // same launched work every call — deterministic and graph-capturable)
    struct Res {
        cudaStream_t s1;
        cudaEvent_t ev_fork, ev_join;
        Res() {
            cudaStreamCreateWithFlags(&s1, cudaStreamNonBlocking);
            cudaEventCreateWithFlags(&ev_fork, cudaEventDisableTiming);
            cudaEventCreateWithFlags(&ev_join, cudaEventDisableTiming);
        }
    };
    static Res R;

    // fork: prefetch W1+W2 into L2 while prep+attn run (they are SM-bound,
    // DRAM is idle in that window)
    cudaEventRecord(R.ev_fork, 0);
    cudaStreamWaitEvent(R.s1, R.ev_fork, 0);
    prefetch_kernel<<<128, 256, 0, R.s1>>>(w1_w, w2_w);
    cudaEventRecord(R.ev_join, R.s1);

    prep_kernel<<<B_, 256>>>(feat, idx, ln_w, ln_b, q_w, k_w, v_w, conv_w);
    attn_kernel<<<dim3(B_, 16), 256>>>(feat, out);
    ffn_prep_kernel<<<B_, 256>>>(bn_w, bn_b, w1_b, w2_b, out);

    // join before the GEMMs consume the prefetched weights
    cudaStreamWaitEvent(0, R.ev_join, 0);
    gemm_kernel<<<dim3(16, 8), 256>>>(0, w1_w, out);
    gemm_kernel<<<dim3(16, 8), 256>>>(1, w2_w, out);
}

// round 16
// speedup vs baseline: 1.0827x; 1.0827x over previous
#include <cuda_runtime.h>
#include <math.h>

#define B_   32
#define DF_  2048
#define NC_  1023
#define NCP_ 1024

typedef unsigned long long ull;

// ---- packed f32x2 helpers ----
__device__ __forceinline__ ull PK(float lo, float hi) {
    ull r; asm("mov.b64 %0,{%1,%2};" : "=l"(r) : "f"(lo), "f"(hi)); return r;
}
__device__ __forceinline__ void UPK(ull v, float& a, float& b) {
    asm("mov.b64 {%0,%1},%2;" : "=f"(a), "=f"(b) : "l"(v));
}
__device__ __forceinline__ ull FMA2(ull a, ull b, ull c) {
    ull d; asm("fma.rn.f32x2 %0,%1,%2,%3;" : "=l"(d) : "l"(a), "l"(b), "l"(c)); return d;
}
__device__ __forceinline__ ull ADD2(ull a, ull b) {
    ull d; asm("add.rn.f32x2 %0,%1,%2;" : "=l"(d) : "l"(a), "l"(b)); return d;
}
__device__ __forceinline__ ull MUL2(ull a, ull b) {
    ull d; asm("mul.rn.f32x2 %0,%1,%2;" : "=l"(d) : "l"(a), "l"(b)); return d;
}

// ---- cp.async helpers ----
__device__ __forceinline__ void cpasync16(void* dst_smem, const void* src) {
    unsigned d = (unsigned)__cvta_generic_to_shared(dst_smem);
    asm volatile("cp.async.cg.shared.global [%0], [%1], 16;" :: "r"(d), "l"(src));
}
__device__ __forceinline__ void cp_commit() {
    asm volatile("cp.async.commit_group;");
}
template <int N>
__device__ __forceinline__ void cp_wait() {
    asm volatile("cp.async.wait_group %0;" :: "n"(N));
}

// ---------------- scratch ----------------
__device__ float g_LN[B_ * DF_];
__device__ float g_S[B_ * NCP_];
__device__ float g_V[B_ * NCP_];
__device__ float g_smax[B_];
__device__ float g_smin[B_];
__device__ float g_OUT1[B_ * DF_];
__device__ float g_LN2[B_ * DF_];
__device__ float g_H[B_ * DF_];
__device__ float g_s1[B_];    // sum of OUT1 row (accumulated by attn)
__device__ float g_s2[B_];    // sum of squares

// ============================================================================
// K1: per-batch preprocess (round-5 + zeroing the OUT1 stats accumulators)
// ============================================================================
__global__ void prep_kernel(const float* __restrict__ feat,
                            const int*   __restrict__ idx,
                            const float* __restrict__ ln_w,
                            const float* __restrict__ ln_b,
                            const float* __restrict__ q_w,
                            const float* __restrict__ k_w,
                            const float* __restrict__ v_w,
                            const float* __restrict__ conv_w) {
    __shared__ float sf[DF_];
    __shared__ float sh[DF_];
    __shared__ float kred[4][128];
    __shared__ float vred[4][128];
    __shared__ float red1[8], red2[8];

    const int b = blockIdx.x;
    const int tid = threadIdx.x;

    if (tid == 0) { g_s1[b] = 0.f; g_s2[b] = 0.f; }

    float s1 = 0.f, s2 = 0.f;
    for (int i = tid; i < DF_; i += 256) {
        float v = feat[b * DF_ + i];
        sf[i] = v;
        s1 += v;
        s2 = fmaf(v, v, s2);
    }

    if (tid < 128) {
        float qw = q_w[tid];
        float cw = conv_w[tid];
        #pragma unroll
        for (int j = 0; j < 4; j++) {
            kred[j][tid] = qw * k_w[tid * 4 + j];
            vred[j][tid] = cw * v_w[tid * 4 + j];
        }
    }

    #pragma unroll
    for (int o = 16; o; o >>= 1) {
        s1 += __shfl_xor_sync(~0u, s1, o);
        s2 += __shfl_xor_sync(~0u, s2, o);
    }
    if ((tid & 31) == 0) { red1[tid >> 5] = s1; red2[tid >> 5] = s2; }
    __syncthreads();

    if (tid < 64) {
        #pragma unroll
        for (int j = 0; j < 4; j++) {
            kred[j][tid] += kred[j][tid + 64];
            vred[j][tid] += vred[j][tid + 64];
        }
    }
    __syncthreads();
    if (tid < 32) {
        #pragma unroll
        for (int j = 0; j < 4; j++) {
            float kv = kred[j][tid] + kred[j][tid + 32];
            float vv = vred[j][tid] + vred[j][tid + 32];
            #pragma unroll
            for (int o = 16; o; o >>= 1) {
                kv += __shfl_xor_sync(~0u, kv, o);
                vv += __shfl_xor_sync(~0u, vv, o);
            }
            if (tid == 0) { kred[j][0] = kv; vred[j][0] = vv; }
        }
    }
    __syncthreads();

    float S1 = 0.f, S2 = 0.f;
    #pragma unroll
    for (int i = 0; i < 8; i++) { S1 += red1[i]; S2 += red2[i]; }
    const float mean = S1 * (1.f / DF_);
    const float var  = S2 * (1.f / DF_) - mean * mean;
    const float rstd = rsqrtf(var + 1e-5f);

    for (int i = tid; i < DF_; i += 256) {
        g_LN[b * DF_ + i] = (sf[i] - mean) * rstd * ln_w[i] + ln_b[i];
        sh[i] = sf[idx[i]];
    }
    __syncthreads();

    const float kw0 = kred[0][0], kw1 = kred[1][0], kw2 = kred[2][0], kw3 = kred[3][0];
    const float vw0 = vred[0][0], vw1 = vred[1][0], vw2 = vred[2][0], vw3 = vred[3][0];

    float lmax = -3.4e38f, lmin = 3.4e38f;
    for (int c = tid; c < NCP_; c += 256) {
        float s = 0.f, v = 0.f;
        if (c < NC_) {
            float x0 = sh[2 * c], x1 = sh[2 * c + 1], x2 = sh[2 * c + 2], x3 = sh[2 * c + 3];
            s = fmaf(x3, kw3, fmaf(x2, kw2, fmaf(x1, kw1, x0 * kw0)));
            v = fmaf(x3, vw3, fmaf(x2, vw2, fmaf(x1, vw1, x0 * vw0)));
            lmax = fmaxf(lmax, s);
            lmin = fminf(lmin, s);
        }
        g_S[b * NCP_ + c] = s;
        g_V[b * NCP_ + c] = v;
    }
    #pragma unroll
    for (int o = 16; o; o >>= 1) {
        lmax = fmaxf(lmax, __shfl_xor_sync(~0u, lmax, o));
        lmin = fminf(lmin, __shfl_xor_sync(~0u, lmin, o));
    }
    __syncthreads();
    if ((tid & 31) == 0) { red1[tid >> 5] = lmax; red2[tid >> 5] = lmin; }
    __syncthreads();
    if (tid == 0) {
        float mx = red1[0], mn = red2[0];
        #pragma unroll
        for (int i = 1; i < 8; i++) { mx = fmaxf(mx, red1[i]); mn = fminf(mn, red2[i]); }
        g_smax[b] = mx;
        g_smin[b] = mn;
    }
}

// ============================================================================
// K2: softmax + attn output (round-5) + OUT1 stats accumulation epilogue
// ============================================================================
#define SBUF_PITCH 1056
__global__ __launch_bounds__(256) void attn_kernel(const float* __restrict__ feat,
                                                   float* __restrict__ dout) {
    __shared__ __align__(16) float sbuf[8 * SBUF_PITCH];
    __shared__ float ps1[8], ps2[8];

    const int b = blockIdx.x;
    const int chunk = blockIdx.y;
    const int tid = threadIdx.x;
    const int lane = tid & 31;
    const int w = tid >> 5;

    const float2* gs = (const float2*)(g_S + b * NCP_);
    const float2* gv = (const float2*)(g_V + b * NCP_);
    ull sreg[16], vreg[16];
    #pragma unroll
    for (int i = 0; i < 16; ++i) {
        float2 s2 = gs[lane + 32 * i];
        float2 v2 = gv[lane + 32 * i];
        sreg[i] = PK(s2.x, s2.y);
        vreg[i] = PK(v2.x, v2.y);
    }

    const float smax = g_smax[b];
    const float smin = g_smin[b];
    const float LOG2E = 1.4426950408889634f;
    const ull C5 = PK(0.00133335581464284f, 0.00133335581464284f);
    const ull C4 = PK(0.00961812910762848f, 0.00961812910762848f);
    const ull C3 = PK(0.05550410866482158f, 0.05550410866482158f);
    const ull C2 = PK(0.24022650695910071f, 0.24022650695910071f);
    const ull C1 = PK(0.69314718055994531f, 0.69314718055994531f);
    const ull ONE = PK(1.0f, 1.0f);

    const bool lastlane = (lane == 31);
    float* const sb = sbuf + w * SBUF_PITCH;

    float o_s1 = 0.f, o_s2 = 0.f;    // lane-0 partials of OUT1 stats

    for (int r = 0; r < 16; ++r) {
        const int q = chunk * 128 + r * 8 + w;
        const int row = b * DF_ + q;
        const float alpha = g_LN[row];
        const float al = alpha * LOG2E;
        const float m = (alpha >= 0.f) ? smax : smin;
        const float nb = -al * m;
        const ull al2 = PK(al, al);
        const ull nb2 = PK(nb, nb);

        ull p2[16];
        ull sum2 = PK(0.f, 0.f), dot2 = PK(0.f, 0.f);
        #pragma unroll
        for (int i = 0; i < 16; ++i) {
            ull x = FMA2(al2, sreg[i], nb2);
            ull pf = FMA2(x, C5, C4);
            pf = FMA2(x, pf, C3);
            pf = FMA2(x, pf, C2);
            pf = FMA2(x, pf, C1);
            pf = FMA2(x, pf, ONE);
            if (i == 15) {
                float a_, b_; UPK(pf, a_, b_);
                if (lastlane) b_ = 0.f;
                pf = PK(a_, b_);
            }
            p2[i] = pf;
            sum2 = ADD2(sum2, pf);
            dot2 = FMA2(pf, vreg[i], dot2);
        }

        float slo, shi, dlo, dhi;
        UPK(sum2, slo, shi);
        UPK(dot2, dlo, dhi);
        float sum = slo + shi;
        float dot = dlo + dhi;
        #pragma unroll
        for (int o = 16; o; o >>= 1) {
            sum += __shfl_xor_sync(~0u, sum, o);
            dot += __shfl_xor_sync(~0u, dot, o);
        }
        const float inv = 1.0f / sum;
        const ull inv2 = PK(inv, inv);

        float* const base = dout + 65536 + (size_t)row * NC_;
        const int shift = (int)((size_t)base & 15) >> 2;
        const int lead = (4 - shift) & 3;

        if ((shift & 1) == 0) {
            #pragma unroll
            for (int i = 0; i < 16; ++i) {
                float o0, o1; UPK(MUL2(p2[i], inv2), o0, o1);
                *(float2*)(sb + 2 * (lane + 32 * i) + shift) = make_float2(o0, o1);
            }
        } else {
            #pragma unroll
            for (int i = 0; i < 16; ++i) {
                float o0, o1; UPK(MUL2(p2[i], inv2), o0, o1);
                const int c = 2 * (lane + 32 * i) + shift;
                sb[c] = o0;
                sb[c + 1] = o1;
            }
        }
        __syncwarp();

        if (lane < lead) __stcs(base + lane, sb[lane + shift]);
        const float4* s4 = (const float4*)(sb + lead + shift);
        float4* g4 = (float4*)(base + lead);
        #pragma unroll
        for (int j = 0; j < 8; ++j) {
            const int t = lane + 32 * j;
            if (t < 255) __stcs(g4 + t, s4[t]);
        }
        const int done = lead + 1020;
        const int tail = NC_ - done;
        if (lane < tail) __stcs(base + done + lane, sb[done + lane + shift]);

        if (lane == 0) {
            float ov = fmaf(dot, inv, feat[row]);
            g_OUT1[row] = ov;
            o_s1 += ov;
            o_s2 = fmaf(ov, ov, o_s2);
        }
        __syncwarp();
    }

    // block-reduce the 8 lane-0 partials and accumulate row stats
    if (lane == 0) { ps1[w] = o_s1; ps2[w] = o_s2; }
    __syncthreads();
    if (tid == 0) {
        float a = 0.f, c = 0.f;
        #pragma unroll
        for (int i = 0; i < 8; ++i) { a += ps1[i]; c += ps2[i]; }
        atomicAdd(&g_s1[b], a);
        atomicAdd(&g_s2[b], c);
    }
}

// ============================================================================
// K3: FFN prep v2 — pure elementwise (stats precomputed by attn).
// grid (32 b, 8 chunks) x 256 thr = 256 CTAs.
// ============================================================================
__global__ __launch_bounds__(256) void ffn_prep_kernel(const float* __restrict__ bn_w,
                                                       const float* __restrict__ bn_b,
                                                       const float* __restrict__ w1_b,
                                                       const float* __restrict__ w2_b,
                                                       float* __restrict__ dout) {
    const int b = blockIdx.x;
    const int i = blockIdx.y * 256 + threadIdx.x;

    const float mean = g_s1[b] * (1.f / DF_);
    const float var  = g_s2[b] * (1.f / DF_) - mean * mean;
    const float rstd = rsqrtf(var + 1e-6f);

    const float v = g_OUT1[b * DF_ + i];
    g_LN2[b * DF_ + i] = (v - mean) * rstd * bn_w[i] + bn_b[i];
    g_H[b * DF_ + i]   = w1_b[i];
    dout[b * DF_ + i]  = w2_b[i] + v;
}

// ============================================================================
// K4/K5: GEMM (round-5 config: 32m x 128n x 256k, grid (16,8), f32x2 FMA)
// ============================================================================
__global__ __launch_bounds__(256) void gemm_kernel(int mode,
                                                   const float* __restrict__ W,
                                                   float* __restrict__ outp) {
    __shared__ __align__(16) float As[256][36];        // [k][m]
    __shared__ __align__(16) float Ws[3][128][36];     // [n][k] stages

    const float* A = (mode == 0) ? g_LN2 : g_H;
    float* C       = (mode == 0) ? g_H   : outp;

    const int n0 = blockIdx.x * 128;
    const int k0 = blockIdx.y * 256;
    const int tid = threadIdx.x;
    const int lane = tid & 31;
    const int wid = tid >> 5;

    auto issueW = [&](int s) {
        const int buf = s % 3;
        #pragma unroll
        for (int j = 0; j < 4; ++j) {
            int idx = tid + 256 * j;
            int n = idx >> 3, qd = idx & 7;
            cpasync16(&Ws[buf][n][qd * 4],
                      &W[(size_t)(n0 + n) * DF_ + k0 + s * 32 + qd * 4]);
        }
        cp_commit();
    };

    issueW(0);
    issueW(1);

    {
        const int m = tid >> 3;
        const int kq = (tid & 7) * 4;
        #pragma unroll
        for (int it = 0; it < 8; ++it) {
            const int k = kq + 32 * it;
            float4 v = *(const float4*)&A[m * DF_ + k0 + k];
            if (mode) {
                v.x = fmaxf(v.x, 0.f); v.y = fmaxf(v.y, 0.f);
                v.z = fmaxf(v.z, 0.f); v.w = fmaxf(v.w, 0.f);
            }
            As[k + 0][m] = v.x;
            As[k + 1][m] = v.y;
            As[k + 2][m] = v.z;
            As[k + 3][m] = v.w;
        }
    }

    const int m0 = (lane & 7) * 4;
    const int nb = wid * 16 + (lane >> 3) * 4;

    ull acc2[4][2];
    #pragma unroll
    for (int u = 0; u < 4; ++u) { acc2[u][0] = PK(0.f, 0.f); acc2[u][1] = PK(0.f, 0.f); }

    #pragma unroll
    for (int s = 0; s < 8; ++s) {
        if (s < 7) cp_wait<1>(); else cp_wait<0>();
        __syncthreads();
        if (s + 2 < 8) issueW(s + 2);

        const int buf = s % 3;
        #pragma unroll
        for (int k4 = 0; k4 < 8; ++k4) {
            const int kk = s * 32 + k4 * 4;
            ull a[4][2];
            #pragma unroll
            for (int k = 0; k < 4; ++k) {
                float4 av = *(const float4*)&As[kk + k][m0];
                a[k][0] = PK(av.x, av.y);
                a[k][1] = PK(av.z, av.w);
            }
            #pragma unroll
            for (int u = 0; u < 4; ++u) {
                float4 wv = *(const float4*)&Ws[buf][nb + u][k4 * 4];
                ull w0 = PK(wv.x, wv.x);
                ull w1 = PK(wv.y, wv.y);
                ull w2 = PK(wv.z, wv.z);
                ull w3 = PK(wv.w, wv.w);
                acc2[u][0] = FMA2(a[0][0], w0, acc2[u][0]);
                acc2[u][1] = FMA2(a[0][1], w0, acc2[u][1]);
                acc2[u][0] = FMA2(a[1][0], w1, acc2[u][0]);
                acc2[u][1] = FMA2(a[1][1], w1, acc2[u][1]);
                acc2[u][0] = FMA2(a[2][0], w2, acc2[u][0]);
                acc2[u][1] = FMA2(a[2][1], w2, acc2[u][1]);
                acc2[u][0] = FMA2(a[3][0], w3, acc2[u][0]);
                acc2[u][1] = FMA2(a[3][1], w3, acc2[u][1]);
            }
        }
    }

    #pragma unroll
    for (int u = 0; u < 4; ++u) {
        float v0, v1, v2, v3;
        UPK(acc2[u][0], v0, v1);
        UPK(acc2[u][1], v2, v3);
        atomicAdd(&C[(m0 + 0) * DF_ + n0 + nb + u], v0);
        atomicAdd(&C[(m0 + 1) * DF_ + n0 + nb + u], v1);
        atomicAdd(&C[(m0 + 2) * DF_ + n0 + nb + u], v2);
        atomicAdd(&C[(m0 + 3) * DF_ + n0 + nb + u], v3);
    }
}

// ============================================================================
extern "C" void kernel_launch(void* const* d_in, const int* in_sizes, int n_in,
                              void* d_out, int out_size) {
    const float* feat   = (const float*)d_in[0];
    const int*   idx    = (const int*)  d_in[1];
    const float* ln_w   = (const float*)d_in[2];
    const float* ln_b   = (const float*)d_in[3];
    const float* q_w    = (const float*)d_in[4];
    const float* k_w    = (const float*)d_in[5];
    const float* v_w    = (const float*)d_in[6];
    const float* conv_w = (const float*)d_in[7];
    const float* bn_w   = (const float*)d_in[8];
    const float* bn_b   = (const float*)d_in[9];
    const float* w1_w   = (const float*)d_in[10];
    const float* w1_b   = (const float*)d_in[11];
    const float* w2_w   = (const float*)d_in[12];
    const float* w2_b   = (const float*)d_in[13];
    float* out = (float*)d_out;

    prep_kernel<<<B_, 256>>>(feat, idx, ln_w, ln_b, q_w, k_w, v_w, conv_w);
    attn_kernel<<<dim3(B_, 16), 256>>>(feat, out);
    ffn_prep_kernel<<<dim3(B_, 8), 256>>>(bn_w, bn_b, w1_b, w2_b, out);
    gemm_kernel<<<dim3(16, 8), 256>>>(0, w1_w, out);
    gemm_kernel<<<dim3(16, 8), 256>>>(1, w2_w, out);
}